// round 1
// baseline (speedup 1.0000x reference)
#include <cuda_runtime.h>
#include <math.h>
#include <stdint.h>

#define B_   4
#define S_   2048
#define D_   1024
#define H_   16
#define DK_  64
#define F_   4096
#define NTOK (B_ * S_)

// ---------------- scratch (device globals: no allocation allowed) ----------
__device__ float g_h[(size_t)NTOK * D_];     // ln1 out, reused as ln2 out
__device__ float g_q[(size_t)NTOK * D_];
__device__ float g_k[(size_t)NTOK * D_];
__device__ float g_v[(size_t)NTOK * D_];
__device__ float g_ctx[(size_t)NTOK * D_];
__device__ float g_a[(size_t)NTOK * F_];     // FFN hidden
__device__ float g_vmean[B_ * D_];           // per (b, h*64+d) mean of V over S

// ---------------- LayerNorm: one block per row, 256 threads ----------------
__global__ __launch_bounds__(256) void ln_kernel(
    const float* __restrict__ x, const float* __restrict__ gamma,
    const float* __restrict__ beta, float* __restrict__ out)
{
    int row = blockIdx.x;
    int tid = threadIdx.x;
    const float* xr = x + (size_t)row * D_;
    float4 v = *(const float4*)(xr + tid * 4);
    float s  = v.x + v.y + v.z + v.w;
    float ss = v.x*v.x + v.y*v.y + v.z*v.z + v.w*v.w;
    #pragma unroll
    for (int o = 16; o > 0; o >>= 1) {
        s  += __shfl_xor_sync(0xffffffffu, s,  o);
        ss += __shfl_xor_sync(0xffffffffu, ss, o);
    }
    __shared__ float2 red[8];
    if ((tid & 31) == 0) red[tid >> 5] = make_float2(s, ss);
    __syncthreads();
    if (tid < 32) {
        float2 r = (tid < 8) ? red[tid] : make_float2(0.f, 0.f);
        s = r.x; ss = r.y;
        #pragma unroll
        for (int o = 4; o > 0; o >>= 1) {
            s  += __shfl_xor_sync(0xffffffffu, s,  o);
            ss += __shfl_xor_sync(0xffffffffu, ss, o);
        }
        if (tid == 0) red[0] = make_float2(s, ss);
    }
    __syncthreads();
    float mu  = red[0].x * (1.0f / D_);
    float var = red[0].y * (1.0f / D_) - mu * mu;
    float inv = rsqrtf(var + 1e-5f);
    float4 g4 = *(const float4*)(gamma + tid * 4);
    float4 b4 = *(const float4*)(beta  + tid * 4);
    float4 o4;
    o4.x = (v.x - mu) * inv * g4.x + b4.x;
    o4.y = (v.y - mu) * inv * g4.y + b4.y;
    o4.z = (v.z - mu) * inv * g4.z + b4.z;
    o4.w = (v.w - mu) * inv * g4.w + b4.w;
    *(float4*)(out + (size_t)row * D_ + tid * 4) = o4;
}

// ---------------- SGEMM 128x128x16, 8x8/thread, fused epilogues ------------
#define EPI_BIAS      0
#define EPI_BIAS_RES  1
#define EPI_BIAS_GELU 2

__device__ __forceinline__ float gelu_exact(float x) {
    return 0.5f * x * (1.0f + erff(x * 0.70710678118654752f));
}

template <int EPI>
__global__ __launch_bounds__(256) void sgemm_kernel(
    const float* __restrict__ A, const float* __restrict__ Bm,
    const float* __restrict__ bias, const float* __restrict__ res,
    float* __restrict__ C, int M, int N, int K)
{
    __shared__ float As[16][128];
    __shared__ float Bs[16][128];
    int tid = threadIdx.x;
    int m0 = blockIdx.y * 128, n0 = blockIdx.x * 128;
    int ty = tid >> 4, tx = tid & 15;

    float acc[8][8];
    #pragma unroll
    for (int i = 0; i < 8; i++)
        #pragma unroll
        for (int j = 0; j < 8; j++) acc[i][j] = 0.f;

    for (int k0 = 0; k0 < K; k0 += 16) {
        #pragma unroll
        for (int l = 0; l < 2; l++) {
            int idx = tid + l * 256;
            int ar = idx >> 2, ac = (idx & 3) << 2;
            float4 av = *(const float4*)(A + (size_t)(m0 + ar) * K + k0 + ac);
            As[ac + 0][ar] = av.x; As[ac + 1][ar] = av.y;
            As[ac + 2][ar] = av.z; As[ac + 3][ar] = av.w;
            int br = idx >> 5, bc = (idx & 31) << 2;
            *(float4*)&Bs[br][bc] = *(const float4*)(Bm + (size_t)(k0 + br) * N + n0 + bc);
        }
        __syncthreads();
        #pragma unroll
        for (int kk = 0; kk < 16; kk++) {
            float a[8], b[8];
            *(float4*)&a[0] = *(float4*)&As[kk][ty * 8];
            *(float4*)&a[4] = *(float4*)&As[kk][ty * 8 + 4];
            *(float4*)&b[0] = *(float4*)&Bs[kk][tx * 8];
            *(float4*)&b[4] = *(float4*)&Bs[kk][tx * 8 + 4];
            #pragma unroll
            for (int i = 0; i < 8; i++)
                #pragma unroll
                for (int j = 0; j < 8; j++)
                    acc[i][j] += a[i] * b[j];
        }
        __syncthreads();
    }

    #pragma unroll
    for (int i = 0; i < 8; i++) {
        int m = m0 + ty * 8 + i;
        #pragma unroll
        for (int j = 0; j < 8; j += 4) {
            int n = n0 + tx * 8 + j;
            float4 o;
            o.x = acc[i][j + 0] + bias[n + 0];
            o.y = acc[i][j + 1] + bias[n + 1];
            o.z = acc[i][j + 2] + bias[n + 2];
            o.w = acc[i][j + 3] + bias[n + 3];
            if (EPI == EPI_BIAS_RES) {
                float4 r = *(const float4*)(res + (size_t)m * N + n);
                o.x += r.x; o.y += r.y; o.z += r.z; o.w += r.w;
            } else if (EPI == EPI_BIAS_GELU) {
                o.x = gelu_exact(o.x); o.y = gelu_exact(o.y);
                o.z = gelu_exact(o.z); o.w = gelu_exact(o.w);
            }
            *(float4*)(C + (size_t)m * N + n) = o;
        }
    }
}

// ---------------- V column means (for fully-masked softmax rows) -----------
__global__ void vmean_zero(float* __restrict__ vmean) {
    vmean[blockIdx.x * 1024 + threadIdx.x] = 0.f;
}
__global__ void vmean_acc(const float* __restrict__ V, float* __restrict__ vmean) {
    int b = blockIdx.x, chunk = blockIdx.y, d = threadIdx.x;
    int s0 = chunk * 256;
    float s = 0.f;
    for (int i = 0; i < 256; i++)
        s += V[(size_t)(b * S_ + s0 + i) * D_ + d];
    atomicAdd(&vmean[b * D_ + d], s * (1.0f / S_));
}

// ---------------- Flash attention, 64x64 tiles, fp32 -----------------------
// thread map: tr = tid>>2 (query row 0..63), tc = tid&3
//   scores : keys  key = tc + 4*ki        (interleaved -> conflict-free Ks LDS.128)
//   output : dims  dd  = tc*16 + i        (contiguous  -> float4 Vs loads)
#define ATT_STRIDE 68
#define ATT_SMEM_BYTES (3 * 64 * ATT_STRIDE * 4)

__global__ __launch_bounds__(256) void attn_kernel(
    const float* __restrict__ Q, const float* __restrict__ K,
    const float* __restrict__ V, const int* __restrict__ mask,
    const float* __restrict__ vmean, float* __restrict__ ctx)
{
    extern __shared__ float sm[];
    float* Qs = sm;
    float* Ks = sm + 64 * ATT_STRIDE;
    float* Vs = sm + 2 * 64 * ATT_STRIDE;
    __shared__ int msk[64];

    int bh = blockIdx.y;
    int b = bh >> 4, h = bh & 15;
    int q0 = blockIdx.x << 6;
    int tid = threadIdx.x;
    int tr = tid >> 2, tc = tid & 3;

    // Q tile, pre-scaled by 1/sqrt(dk) = 0.125
    #pragma unroll
    for (int l = 0; l < 4; l++) {
        int idx = tid + l * 256;
        int r = idx >> 4, c = (idx & 15) << 2;
        float4 qv = *(const float4*)(Q + (size_t)(b * S_ + q0 + r) * D_ + h * DK_ + c);
        qv.x *= 0.125f; qv.y *= 0.125f; qv.z *= 0.125f; qv.w *= 0.125f;
        *(float4*)&Qs[r * ATT_STRIDE + c] = qv;
    }

    float o[16];
    #pragma unroll
    for (int i = 0; i < 16; i++) o[i] = 0.f;
    float mrow = -3.0e38f, lrow = 0.f;

    int jmax = (q0 + 63) >> 6;
    for (int j = 0; j <= jmax; j++) {
        int k0 = j << 6;
        __syncthreads();   // previous-iteration readers done
        #pragma unroll
        for (int l = 0; l < 4; l++) {
            int idx = tid + l * 256;
            int r = idx >> 4, c = (idx & 15) << 2;
            *(float4*)&Ks[r * ATT_STRIDE + c] =
                *(const float4*)(K + (size_t)(b * S_ + k0 + r) * D_ + h * DK_ + c);
            *(float4*)&Vs[r * ATT_STRIDE + c] =
                *(const float4*)(V + (size_t)(b * S_ + k0 + r) * D_ + h * DK_ + c);
        }
        if (tid < 64) msk[tid] = mask[b * S_ + k0 + tid];
        __syncthreads();

        // ---- scores (this thread: 16 keys = tc + 4*ki) ----
        float s[16];
        #pragma unroll
        for (int ki = 0; ki < 16; ki++) s[ki] = 0.f;
        #pragma unroll
        for (int d4 = 0; d4 < 16; d4++) {
            float4 qv = *(float4*)&Qs[tr * ATT_STRIDE + d4 * 4];
            #pragma unroll
            for (int ki = 0; ki < 16; ki++) {
                float4 kv = *(float4*)&Ks[(tc + 4 * ki) * ATT_STRIDE + d4 * 4];
                s[ki] += qv.x * kv.x + qv.y * kv.y + qv.z * kv.z + qv.w * kv.w;
            }
        }
        #pragma unroll
        for (int ki = 0; ki < 16; ki++) {
            int key = tc + 4 * ki;
            int kg = k0 + key;
            if (kg > q0 + tr || msk[key] == 0) s[ki] = -1.0e9f;  // matches reference NEG
        }

        // ---- online softmax (row shared among 4 lanes) ----
        float mt = s[0];
        #pragma unroll
        for (int ki = 1; ki < 16; ki++) mt = fmaxf(mt, s[ki]);
        mt = fmaxf(mt, __shfl_xor_sync(0xffffffffu, mt, 1));
        mt = fmaxf(mt, __shfl_xor_sync(0xffffffffu, mt, 2));
        float mnew  = fmaxf(mrow, mt);
        float scale = expf(mrow - mnew);
        float lsum = 0.f;
        #pragma unroll
        for (int ki = 0; ki < 16; ki++) { s[ki] = expf(s[ki] - mnew); lsum += s[ki]; }
        lsum += __shfl_xor_sync(0xffffffffu, lsum, 1);
        lsum += __shfl_xor_sync(0xffffffffu, lsum, 2);
        lrow = lrow * scale + lsum;
        mrow = mnew;
        #pragma unroll
        for (int i = 0; i < 16; i++) o[i] *= scale;

        // ---- P @ V : broadcast p across the 4 lanes of this row ----
        #pragma unroll
        for (int src = 0; src < 4; src++) {
            #pragma unroll
            for (int ki = 0; ki < 16; ki++) {
                float pk = __shfl_sync(0xffffffffu, s[ki], src, 4);
                const float* vrow = &Vs[(src + 4 * ki) * ATT_STRIDE + tc * 16];
                #pragma unroll
                for (int i4 = 0; i4 < 16; i4 += 4) {
                    float4 vv = *(const float4*)(vrow + i4);
                    o[i4 + 0] += pk * vv.x; o[i4 + 1] += pk * vv.y;
                    o[i4 + 2] += pk * vv.z; o[i4 + 3] += pk * vv.w;
                }
            }
        }
    }

    // epilogue. Fully-masked rows (mrow == -1e9): reference softmax over ALL S
    // equal NEG scores -> uniform 1/S over all keys -> column mean of V.
    float invl = 1.0f / lrow;
    bool degen = (mrow < -1.0e8f);
    size_t base = (size_t)(b * S_ + q0 + tr) * D_ + h * DK_ + tc * 16;
    const float* vm = vmean + b * D_ + h * DK_ + tc * 16;
    #pragma unroll
    for (int i4 = 0; i4 < 16; i4 += 4) {
        float4 ov;
        ov.x = degen ? vm[i4 + 0] : o[i4 + 0] * invl;
        ov.y = degen ? vm[i4 + 1] : o[i4 + 1] * invl;
        ov.z = degen ? vm[i4 + 2] : o[i4 + 2] * invl;
        ov.w = degen ? vm[i4 + 3] : o[i4 + 3] * invl;
        *(float4*)(ctx + base + i4) = ov;
    }
}

// ---------------- launch ---------------------------------------------------
extern "C" void kernel_launch(void* const* d_in, const int* in_sizes, int n_in,
                              void* d_out, int out_size)
{
    (void)in_sizes; (void)n_in; (void)out_size;
    const float* x     = (const float*)d_in[0];
    const int*   amask = (const int*)  d_in[1];
    const float* Wq = (const float*)d_in[2];  const float* bq = (const float*)d_in[3];
    const float* Wk = (const float*)d_in[4];  const float* bk = (const float*)d_in[5];
    const float* Wv = (const float*)d_in[6];  const float* bv = (const float*)d_in[7];
    const float* Wo = (const float*)d_in[8];  const float* bo = (const float*)d_in[9];
    const float* W1 = (const float*)d_in[10]; const float* b1 = (const float*)d_in[11];
    const float* W2 = (const float*)d_in[12]; const float* b2 = (const float*)d_in[13];
    const float* g1 = (const float*)d_in[14]; const float* be1 = (const float*)d_in[15];
    const float* g2 = (const float*)d_in[16]; const float* be2 = (const float*)d_in[17];
    float* out = (float*)d_out;

    float *h, *q, *k, *v, *ctx, *a, *vmean;
    cudaGetSymbolAddress((void**)&h,     g_h);
    cudaGetSymbolAddress((void**)&q,     g_q);
    cudaGetSymbolAddress((void**)&k,     g_k);
    cudaGetSymbolAddress((void**)&v,     g_v);
    cudaGetSymbolAddress((void**)&ctx,   g_ctx);
    cudaGetSymbolAddress((void**)&a,     g_a);
    cudaGetSymbolAddress((void**)&vmean, g_vmean);

    cudaFuncSetAttribute(attn_kernel, cudaFuncAttributeMaxDynamicSharedMemorySize,
                         ATT_SMEM_BYTES);

    dim3 gD(D_ / 128, NTOK / 128);   // N=1024 GEMMs
    dim3 gF(F_ / 128, NTOK / 128);   // N=4096 GEMM

    // attention sublayer (pre-norm)
    ln_kernel<<<NTOK, 256>>>(x, g1, be1, h);
    sgemm_kernel<EPI_BIAS><<<gD, 256>>>(h, Wq, bq, nullptr, q, NTOK, D_, D_);
    sgemm_kernel<EPI_BIAS><<<gD, 256>>>(h, Wk, bk, nullptr, k, NTOK, D_, D_);
    sgemm_kernel<EPI_BIAS><<<gD, 256>>>(h, Wv, bv, nullptr, v, NTOK, D_, D_);
    vmean_zero<<<4, 1024>>>(vmean);
    vmean_acc<<<dim3(4, 8), 1024>>>(v, vmean);
    attn_kernel<<<dim3(S_ / 64, B_ * H_), 256, ATT_SMEM_BYTES>>>(q, k, v, amask, vmean, ctx);
    sgemm_kernel<EPI_BIAS_RES><<<gD, 256>>>(ctx, Wo, bo, x, out, NTOK, D_, D_);

    // FFN sublayer (pre-norm)
    ln_kernel<<<NTOK, 256>>>(out, g2, be2, h);
    sgemm_kernel<EPI_BIAS_GELU><<<gF, 256>>>(h, W1, b1, nullptr, a, NTOK, F_, D_);
    sgemm_kernel<EPI_BIAS_RES><<<gD, 256>>>(a, W2, b2, out, out, NTOK, D_, F_);
}

// round 3
// speedup vs baseline: 1.5635x; 1.5635x over previous
#include <cuda_runtime.h>
#include <cuda_bf16.h>
#include <math.h>
#include <stdint.h>

#define B_   4
#define S_   2048
#define D_   1024
#define H_   16
#define DK_  64
#define F_   4096
#define NTOK (B_ * S_)

// ---------------- scratch (device globals: no allocation allowed) ----------
__device__ float g_h[(size_t)NTOK * D_];     // ln1 out, reused as ln2 out
__device__ float g_q[(size_t)NTOK * D_];
__device__ float g_k[(size_t)NTOK * D_];
__device__ float g_v[(size_t)NTOK * D_];
__device__ float g_ctx[(size_t)NTOK * D_];
__device__ float g_a[(size_t)NTOK * F_];     // FFN hidden
__device__ float g_vmean[B_ * D_];
// transposed weights [N, K]
__device__ float g_wqt[(size_t)D_ * D_];
__device__ float g_wkt[(size_t)D_ * D_];
__device__ float g_wvt[(size_t)D_ * D_];
__device__ float g_wot[(size_t)D_ * D_];
__device__ float g_w1t[(size_t)F_ * D_];
__device__ float g_w2t[(size_t)D_ * F_];

// ======================= helpers ============================================
__device__ __forceinline__ uint32_t smem_u32(const void* p) {
    uint32_t a;
    asm("{ .reg .u64 t; cvta.to.shared.u64 t, %1; cvt.u32.u64 %0, t; }"
        : "=r"(a) : "l"(p));
    return a;
}

__device__ __forceinline__ void ldsm_x4(uint32_t* r, uint32_t addr) {
    asm volatile("ldmatrix.sync.aligned.m8n8.x4.shared.b16 {%0,%1,%2,%3}, [%4];"
        : "=r"(r[0]), "=r"(r[1]), "=r"(r[2]), "=r"(r[3]) : "r"(addr));
}

__device__ __forceinline__ void mma_bf16(float* c, const uint32_t* a,
                                         uint32_t b0, uint32_t b1) {
    asm volatile(
        "mma.sync.aligned.m16n8k16.row.col.f32.bf16.bf16.f32 "
        "{%0,%1,%2,%3}, {%4,%5,%6,%7}, {%8,%9}, {%0,%1,%2,%3};"
        : "+f"(c[0]), "+f"(c[1]), "+f"(c[2]), "+f"(c[3])
        : "r"(a[0]), "r"(a[1]), "r"(a[2]), "r"(a[3]), "r"(b0), "r"(b1));
}

__device__ __forceinline__ void cvt_hilo(float4 v, uint2& hp, uint2& lp) {
    __nv_bfloat162 h01 = make_bfloat162(__float2bfloat16_rn(v.x), __float2bfloat16_rn(v.y));
    __nv_bfloat162 h23 = make_bfloat162(__float2bfloat16_rn(v.z), __float2bfloat16_rn(v.w));
    float lx = v.x - __bfloat162float(h01.x);
    float ly = v.y - __bfloat162float(h01.y);
    float lz = v.z - __bfloat162float(h23.x);
    float lw = v.w - __bfloat162float(h23.y);
    __nv_bfloat162 l01 = make_bfloat162(__float2bfloat16_rn(lx), __float2bfloat16_rn(ly));
    __nv_bfloat162 l23 = make_bfloat162(__float2bfloat16_rn(lz), __float2bfloat16_rn(lw));
    hp = make_uint2(*(uint32_t*)&h01, *(uint32_t*)&h23);
    lp = make_uint2(*(uint32_t*)&l01, *(uint32_t*)&l23);
}

__device__ __forceinline__ float gelu_exact(float x) {
    return 0.5f * x * (1.0f + erff(x * 0.70710678118654752f));
}

// ======================= weight transpose ===================================
__global__ __launch_bounds__(256) void transpose_kernel(
    const float* __restrict__ W, float* __restrict__ Wt, int R, int C)
{
    __shared__ float t[32][33];
    int c0 = blockIdx.x * 32, r0 = blockIdx.y * 32;
    int tx = threadIdx.x, ty = threadIdx.y;  // (32, 8)
    #pragma unroll
    for (int i = 0; i < 32; i += 8)
        t[ty + i][tx] = W[(size_t)(r0 + ty + i) * C + c0 + tx];
    __syncthreads();
    #pragma unroll
    for (int i = 0; i < 32; i += 8)
        Wt[(size_t)(c0 + ty + i) * R + r0 + tx] = t[tx][ty + i];
}

// ======================= LayerNorm ==========================================
__global__ __launch_bounds__(256) void ln_kernel(
    const float* __restrict__ x, const float* __restrict__ gamma,
    const float* __restrict__ beta, float* __restrict__ out)
{
    int row = blockIdx.x;
    int tid = threadIdx.x;
    const float* xr = x + (size_t)row * D_;
    float4 v = *(const float4*)(xr + tid * 4);
    float s  = v.x + v.y + v.z + v.w;
    float ss = v.x*v.x + v.y*v.y + v.z*v.z + v.w*v.w;
    #pragma unroll
    for (int o = 16; o > 0; o >>= 1) {
        s  += __shfl_xor_sync(0xffffffffu, s,  o);
        ss += __shfl_xor_sync(0xffffffffu, ss, o);
    }
    __shared__ float2 red[8];
    if ((tid & 31) == 0) red[tid >> 5] = make_float2(s, ss);
    __syncthreads();
    if (tid < 32) {
        float2 r = (tid < 8) ? red[tid] : make_float2(0.f, 0.f);
        s = r.x; ss = r.y;
        #pragma unroll
        for (int o = 4; o > 0; o >>= 1) {
            s  += __shfl_xor_sync(0xffffffffu, s,  o);
            ss += __shfl_xor_sync(0xffffffffu, ss, o);
        }
        if (tid == 0) red[0] = make_float2(s, ss);
    }
    __syncthreads();
    float mu  = red[0].x * (1.0f / D_);
    float var = red[0].y * (1.0f / D_) - mu * mu;
    float inv = rsqrtf(var + 1e-5f);
    float4 g4 = *(const float4*)(gamma + tid * 4);
    float4 b4 = *(const float4*)(beta  + tid * 4);
    float4 o4;
    o4.x = (v.x - mu) * inv * g4.x + b4.x;
    o4.y = (v.y - mu) * inv * g4.y + b4.y;
    o4.z = (v.z - mu) * inv * g4.z + b4.z;
    o4.w = (v.w - mu) * inv * g4.w + b4.w;
    *(float4*)(out + (size_t)row * D_ + tid * 4) = o4;
}

// ======================= HMMA GEMM (mma.sync bf16 hi/lo) ====================
// C[M,N] = A[M,K] @ Bt[N,K]^T.  Tile 128x128, BK=32, 8 warps (4x2), 32x64/warp.
#define EPI_BIAS      0
#define EPI_BIAS_RES  1
#define EPI_BIAS_GELU 2

// smem layout per stage: A_hi, A_lo, B_hi, B_lo, each 128 rows x 80 bytes
#define ROWB   80u
#define REG_SZ (128u * ROWB)      // 10240
#define OFF_AH 0u
#define OFF_AL (REG_SZ)
#define OFF_BH (2u * REG_SZ)
#define OFF_BL (3u * REG_SZ)
#define STAGE  (4u * REG_SZ)      // 40960
#define MGEMM_SMEM (2 * STAGE)    // 81920

template <int EPI>
__global__ __launch_bounds__(256) void mgemm_kernel(
    const float* __restrict__ A, const float* __restrict__ Bt,
    const float* __restrict__ bias, const float* __restrict__ res,
    float* __restrict__ C, int M, int N, int K)
{
    extern __shared__ __align__(128) char smem[];
    uint32_t sb = smem_u32(smem);
    int tid = threadIdx.x;
    int lane = tid & 31, wid = tid >> 5;
    int wm = wid >> 1, wn = wid & 1;           // 4 x 2 warp grid
    int m0 = blockIdx.y * 128, n0 = blockIdx.x * 128;

    // ldmatrix lane addresses (A: m16k16 x4; B: n16k16 x4)
    uint32_t aOff = (uint32_t)(wm * 32 + (lane & 15)) * ROWB + ((lane >> 4) << 4);
    uint32_t bOff = (uint32_t)(wn * 64 + (lane & 7) + ((lane >> 4) << 3)) * ROWB
                  + (((lane >> 3) & 1) << 4);

    float acc[2][8][4];
    #pragma unroll
    for (int mi = 0; mi < 2; mi++)
        #pragma unroll
        for (int ni = 0; ni < 8; ni++)
            #pragma unroll
            for (int c = 0; c < 4; c++) acc[mi][ni][c] = 0.f;

    // thread's gmem->smem mapping: 4 float4 each for A and B per stage
    int lr[4], lk[4];
    #pragma unroll
    for (int p = 0; p < 4; p++) {
        int idx = tid + p * 256;
        lr[p] = idx >> 3;           // row 0..127
        lk[p] = (idx & 7) << 2;     // k offset 0..28
    }

    // ---- load stage 0 directly ----
    {
        const int k0 = 0;
        #pragma unroll
        for (int p = 0; p < 4; p++) {
            float4 va = *(const float4*)(A  + (size_t)(m0 + lr[p]) * K + k0 + lk[p]);
            float4 vb = *(const float4*)(Bt + (size_t)(n0 + lr[p]) * K + k0 + lk[p]);
            uint2 hp, lp;
            uint32_t ro = (uint32_t)lr[p] * ROWB + (uint32_t)lk[p] * 2;
            cvt_hilo(va, hp, lp);
            *(uint2*)(smem + OFF_AH + ro) = hp;
            *(uint2*)(smem + OFF_AL + ro) = lp;
            cvt_hilo(vb, hp, lp);
            *(uint2*)(smem + OFF_BH + ro) = hp;
            *(uint2*)(smem + OFF_BL + ro) = lp;
        }
    }
    __syncthreads();

    const int nIter = K >> 5;
    for (int i = 0; i < nIter; i++) {
        uint32_t st = (uint32_t)(i & 1) * STAGE;

        // prefetch next chunk into registers
        float4 pa[4], pb[4];
        if (i + 1 < nIter) {
            int k0 = (i + 1) << 5;
            #pragma unroll
            for (int p = 0; p < 4; p++) {
                pa[p] = *(const float4*)(A  + (size_t)(m0 + lr[p]) * K + k0 + lk[p]);
                pb[p] = *(const float4*)(Bt + (size_t)(n0 + lr[p]) * K + k0 + lk[p]);
            }
        }

        // compute on current stage
        #pragma unroll
        for (int ks = 0; ks < 2; ks++) {
            uint32_t ko = (uint32_t)ks * 32;
            uint32_t a_h[2][4], a_l[2][4], b_h[4][4], b_l[4][4];
            #pragma unroll
            for (int mi = 0; mi < 2; mi++) {
                ldsm_x4(a_h[mi], sb + st + OFF_AH + aOff + ko + (uint32_t)mi * 16 * ROWB);
                ldsm_x4(a_l[mi], sb + st + OFF_AL + aOff + ko + (uint32_t)mi * 16 * ROWB);
            }
            #pragma unroll
            for (int nj = 0; nj < 4; nj++) {
                ldsm_x4(b_h[nj], sb + st + OFF_BH + bOff + ko + (uint32_t)nj * 16 * ROWB);
                ldsm_x4(b_l[nj], sb + st + OFF_BL + bOff + ko + (uint32_t)nj * 16 * ROWB);
            }
            #pragma unroll
            for (int mi = 0; mi < 2; mi++) {
                #pragma unroll
                for (int nj = 0; nj < 4; nj++) {
                    mma_bf16(acc[mi][2*nj],   a_h[mi], b_h[nj][0], b_h[nj][1]);
                    mma_bf16(acc[mi][2*nj+1], a_h[mi], b_h[nj][2], b_h[nj][3]);
                    mma_bf16(acc[mi][2*nj],   a_h[mi], b_l[nj][0], b_l[nj][1]);
                    mma_bf16(acc[mi][2*nj+1], a_h[mi], b_l[nj][2], b_l[nj][3]);
                    mma_bf16(acc[mi][2*nj],   a_l[mi], b_h[nj][0], b_h[nj][1]);
                    mma_bf16(acc[mi][2*nj+1], a_l[mi], b_h[nj][2], b_h[nj][3]);
                }
            }
        }

        // store prefetched chunk into the other stage
        if (i + 1 < nIter) {
            char* dst = smem + ((i & 1) ? 0u : STAGE);
            #pragma unroll
            for (int p = 0; p < 4; p++) {
                uint2 hp, lp;
                uint32_t ro = (uint32_t)lr[p] * ROWB + (uint32_t)lk[p] * 2;
                cvt_hilo(pa[p], hp, lp);
                *(uint2*)(dst + OFF_AH + ro) = hp;
                *(uint2*)(dst + OFF_AL + ro) = lp;
                cvt_hilo(pb[p], hp, lp);
                *(uint2*)(dst + OFF_BH + ro) = hp;
                *(uint2*)(dst + OFF_BL + ro) = lp;
            }
            __syncthreads();
        }
    }

    // ---- epilogue: regs -> gmem (float2), fused bias/res/gelu ----
    #pragma unroll
    for (int mi = 0; mi < 2; mi++) {
        #pragma unroll
        for (int ni = 0; ni < 8; ni++) {
            int row = m0 + wm * 32 + mi * 16 + (lane >> 2);
            int col = n0 + wn * 64 + ni * 8 + ((lane & 3) << 1);
            float* c = acc[mi][ni];
            float2 bi = *(const float2*)(bias + col);
            float2 o0 = make_float2(c[0] + bi.x, c[1] + bi.y);
            float2 o1 = make_float2(c[2] + bi.x, c[3] + bi.y);
            if (EPI == EPI_BIAS_RES) {
                float2 r0 = *(const float2*)(res + (size_t)row * N + col);
                float2 r1 = *(const float2*)(res + (size_t)(row + 8) * N + col);
                o0.x += r0.x; o0.y += r0.y; o1.x += r1.x; o1.y += r1.y;
            } else if (EPI == EPI_BIAS_GELU) {
                o0.x = gelu_exact(o0.x); o0.y = gelu_exact(o0.y);
                o1.x = gelu_exact(o1.x); o1.y = gelu_exact(o1.y);
            }
            *(float2*)(C + (size_t)row * N + col)       = o0;
            *(float2*)(C + (size_t)(row + 8) * N + col) = o1;
        }
    }
}

// ---------------- V column means (for fully-masked softmax rows) -----------
__global__ void vmean_zero(float* __restrict__ vmean) {
    vmean[blockIdx.x * 1024 + threadIdx.x] = 0.f;
}
__global__ void vmean_acc(const float* __restrict__ V, float* __restrict__ vmean) {
    int b = blockIdx.x, chunk = blockIdx.y, d = threadIdx.x;
    int s0 = chunk * 256;
    float s = 0.f;
    for (int i = 0; i < 256; i++)
        s += V[(size_t)(b * S_ + s0 + i) * D_ + d];
    atomicAdd(&vmean[b * D_ + d], s * (1.0f / S_));
}

// ---------------- Flash attention, 64x64 tiles, fp32 -----------------------
#define ATT_STRIDE 68
#define ATT_SMEM_BYTES (3 * 64 * ATT_STRIDE * 4)

__global__ __launch_bounds__(256) void attn_kernel(
    const float* __restrict__ Q, const float* __restrict__ K,
    const float* __restrict__ V, const int* __restrict__ mask,
    const float* __restrict__ vmean, float* __restrict__ ctx)
{
    extern __shared__ float sm[];
    float* Qs = sm;
    float* Ks = sm + 64 * ATT_STRIDE;
    float* Vs = sm + 2 * 64 * ATT_STRIDE;
    __shared__ int msk[64];

    int bh = blockIdx.y;
    int b = bh >> 4, h = bh & 15;
    int q0 = blockIdx.x << 6;
    int tid = threadIdx.x;
    int tr = tid >> 2, tc = tid & 3;

    #pragma unroll
    for (int l = 0; l < 4; l++) {
        int idx = tid + l * 256;
        int r = idx >> 4, c = (idx & 15) << 2;
        float4 qv = *(const float4*)(Q + (size_t)(b * S_ + q0 + r) * D_ + h * DK_ + c);
        qv.x *= 0.125f; qv.y *= 0.125f; qv.z *= 0.125f; qv.w *= 0.125f;
        *(float4*)&Qs[r * ATT_STRIDE + c] = qv;
    }

    float o[16];
    #pragma unroll
    for (int i = 0; i < 16; i++) o[i] = 0.f;
    float mrow = -3.0e38f, lrow = 0.f;

    int jmax = (q0 + 63) >> 6;
    for (int j = 0; j <= jmax; j++) {
        int k0 = j << 6;
        __syncthreads();
        #pragma unroll
        for (int l = 0; l < 4; l++) {
            int idx = tid + l * 256;
            int r = idx >> 4, c = (idx & 15) << 2;
            *(float4*)&Ks[r * ATT_STRIDE + c] =
                *(const float4*)(K + (size_t)(b * S_ + k0 + r) * D_ + h * DK_ + c);
            *(float4*)&Vs[r * ATT_STRIDE + c] =
                *(const float4*)(V + (size_t)(b * S_ + k0 + r) * D_ + h * DK_ + c);
        }
        if (tid < 64) msk[tid] = mask[b * S_ + k0 + tid];
        __syncthreads();

        float s[16];
        #pragma unroll
        for (int ki = 0; ki < 16; ki++) s[ki] = 0.f;
        #pragma unroll
        for (int d4 = 0; d4 < 16; d4++) {
            float4 qv = *(float4*)&Qs[tr * ATT_STRIDE + d4 * 4];
            #pragma unroll
            for (int ki = 0; ki < 16; ki++) {
                float4 kv = *(float4*)&Ks[(tc + 4 * ki) * ATT_STRIDE + d4 * 4];
                s[ki] += qv.x * kv.x + qv.y * kv.y + qv.z * kv.z + qv.w * kv.w;
            }
        }
        #pragma unroll
        for (int ki = 0; ki < 16; ki++) {
            int key = tc + 4 * ki;
            int kg = k0 + key;
            if (kg > q0 + tr || msk[key] == 0) s[ki] = -1.0e9f;
        }

        float mt = s[0];
        #pragma unroll
        for (int ki = 1; ki < 16; ki++) mt = fmaxf(mt, s[ki]);
        mt = fmaxf(mt, __shfl_xor_sync(0xffffffffu, mt, 1));
        mt = fmaxf(mt, __shfl_xor_sync(0xffffffffu, mt, 2));
        float mnew  = fmaxf(mrow, mt);
        float scale = expf(mrow - mnew);
        float lsum = 0.f;
        #pragma unroll
        for (int ki = 0; ki < 16; ki++) { s[ki] = expf(s[ki] - mnew); lsum += s[ki]; }
        lsum += __shfl_xor_sync(0xffffffffu, lsum, 1);
        lsum += __shfl_xor_sync(0xffffffffu, lsum, 2);
        lrow = lrow * scale + lsum;
        mrow = mnew;
        #pragma unroll
        for (int i = 0; i < 16; i++) o[i] *= scale;

        #pragma unroll
        for (int src = 0; src < 4; src++) {
            #pragma unroll
            for (int ki = 0; ki < 16; ki++) {
                float pk = __shfl_sync(0xffffffffu, s[ki], src, 4);
                const float* vrow = &Vs[(src + 4 * ki) * ATT_STRIDE + tc * 16];
                #pragma unroll
                for (int i4 = 0; i4 < 16; i4 += 4) {
                    float4 vv = *(const float4*)(vrow + i4);
                    o[i4 + 0] += pk * vv.x; o[i4 + 1] += pk * vv.y;
                    o[i4 + 2] += pk * vv.z; o[i4 + 3] += pk * vv.w;
                }
            }
        }
    }

    float invl = 1.0f / lrow;
    bool degen = (mrow < -1.0e8f);
    size_t base = (size_t)(b * S_ + q0 + tr) * D_ + h * DK_ + tc * 16;
    const float* vm = vmean + b * D_ + h * DK_ + tc * 16;
    #pragma unroll
    for (int i4 = 0; i4 < 16; i4 += 4) {
        float4 ov;
        ov.x = degen ? vm[i4 + 0] : o[i4 + 0] * invl;
        ov.y = degen ? vm[i4 + 1] : o[i4 + 1] * invl;
        ov.z = degen ? vm[i4 + 2] : o[i4 + 2] * invl;
        ov.w = degen ? vm[i4 + 3] : o[i4 + 3] * invl;
        *(float4*)(ctx + base + i4) = ov;
    }
}

// ---------------- launch ---------------------------------------------------
extern "C" void kernel_launch(void* const* d_in, const int* in_sizes, int n_in,
                              void* d_out, int out_size)
{
    (void)in_sizes; (void)n_in; (void)out_size;
    const float* x     = (const float*)d_in[0];
    const int*   amask = (const int*)  d_in[1];
    const float* Wq = (const float*)d_in[2];  const float* bq = (const float*)d_in[3];
    const float* Wk = (const float*)d_in[4];  const float* bk = (const float*)d_in[5];
    const float* Wv = (const float*)d_in[6];  const float* bv = (const float*)d_in[7];
    const float* Wo = (const float*)d_in[8];  const float* bo = (const float*)d_in[9];
    const float* W1 = (const float*)d_in[10]; const float* b1 = (const float*)d_in[11];
    const float* W2 = (const float*)d_in[12]; const float* b2 = (const float*)d_in[13];
    const float* g1 = (const float*)d_in[14]; const float* be1 = (const float*)d_in[15];
    const float* g2 = (const float*)d_in[16]; const float* be2 = (const float*)d_in[17];
    float* out = (float*)d_out;

    float *h, *q, *k, *v, *ctx, *a, *vmean;
    float *wqt, *wkt, *wvt, *wot, *w1t, *w2t;
    cudaGetSymbolAddress((void**)&h,     g_h);
    cudaGetSymbolAddress((void**)&q,     g_q);
    cudaGetSymbolAddress((void**)&k,     g_k);
    cudaGetSymbolAddress((void**)&v,     g_v);
    cudaGetSymbolAddress((void**)&ctx,   g_ctx);
    cudaGetSymbolAddress((void**)&a,     g_a);
    cudaGetSymbolAddress((void**)&vmean, g_vmean);
    cudaGetSymbolAddress((void**)&wqt,   g_wqt);
    cudaGetSymbolAddress((void**)&wkt,   g_wkt);
    cudaGetSymbolAddress((void**)&wvt,   g_wvt);
    cudaGetSymbolAddress((void**)&wot,   g_wot);
    cudaGetSymbolAddress((void**)&w1t,   g_w1t);
    cudaGetSymbolAddress((void**)&w2t,   g_w2t);

    cudaFuncSetAttribute(attn_kernel, cudaFuncAttributeMaxDynamicSharedMemorySize,
                         ATT_SMEM_BYTES);
    cudaFuncSetAttribute(mgemm_kernel<EPI_BIAS>,      cudaFuncAttributeMaxDynamicSharedMemorySize, MGEMM_SMEM);
    cudaFuncSetAttribute(mgemm_kernel<EPI_BIAS_RES>,  cudaFuncAttributeMaxDynamicSharedMemorySize, MGEMM_SMEM);
    cudaFuncSetAttribute(mgemm_kernel<EPI_BIAS_GELU>, cudaFuncAttributeMaxDynamicSharedMemorySize, MGEMM_SMEM);

    dim3 tb(32, 8);
    transpose_kernel<<<dim3(D_ / 32, D_ / 32), tb>>>(Wq, wqt, D_, D_);
    transpose_kernel<<<dim3(D_ / 32, D_ / 32), tb>>>(Wk, wkt, D_, D_);
    transpose_kernel<<<dim3(D_ / 32, D_ / 32), tb>>>(Wv, wvt, D_, D_);
    transpose_kernel<<<dim3(D_ / 32, D_ / 32), tb>>>(Wo, wot, D_, D_);
    transpose_kernel<<<dim3(F_ / 32, D_ / 32), tb>>>(W1, w1t, D_, F_);
    transpose_kernel<<<dim3(D_ / 32, F_ / 32), tb>>>(W2, w2t, F_, D_);

    dim3 gD(D_ / 128, NTOK / 128);   // (8, 64)
    dim3 gF(F_ / 128, NTOK / 128);   // (32, 64)

    // attention sublayer (pre-norm)
    ln_kernel<<<NTOK, 256>>>(x, g1, be1, h);
    mgemm_kernel<EPI_BIAS><<<gD, 256, MGEMM_SMEM>>>(h, wqt, bq, nullptr, q, NTOK, D_, D_);
    mgemm_kernel<EPI_BIAS><<<gD, 256, MGEMM_SMEM>>>(h, wkt, bk, nullptr, k, NTOK, D_, D_);
    mgemm_kernel<EPI_BIAS><<<gD, 256, MGEMM_SMEM>>>(h, wvt, bv, nullptr, v, NTOK, D_, D_);
    vmean_zero<<<4, 1024>>>(vmean);
    vmean_acc<<<dim3(4, 8), 1024>>>(v, vmean);
    attn_kernel<<<dim3(S_ / 64, B_ * H_), 256, ATT_SMEM_BYTES>>>(q, k, v, amask, vmean, ctx);
    mgemm_kernel<EPI_BIAS_RES><<<gD, 256, MGEMM_SMEM>>>(ctx, wot, bo, x, out, NTOK, D_, D_);

    // FFN sublayer (pre-norm)
    ln_kernel<<<NTOK, 256>>>(out, g2, be2, h);
    mgemm_kernel<EPI_BIAS_GELU><<<gF, 256, MGEMM_SMEM>>>(h, w1t, b1, nullptr, a, NTOK, F_, D_);
    mgemm_kernel<EPI_BIAS_RES><<<gD, 256, MGEMM_SMEM>>>(a, w2t, b2, out, out, NTOK, D_, F_);
}

// round 4
// speedup vs baseline: 3.2600x; 2.0850x over previous
#include <cuda_runtime.h>
#include <cuda_bf16.h>
#include <math.h>
#include <stdint.h>

#define B_   4
#define S_   2048
#define D_   1024
#define H_   16
#define DK_  64
#define F_   4096
#define NTOK (B_ * S_)

// ---------------- scratch (device globals: no allocation allowed) ----------
__device__ float g_h[(size_t)NTOK * D_];
__device__ float g_q[(size_t)NTOK * D_];
__device__ float g_k[(size_t)NTOK * D_];
__device__ float g_v[(size_t)NTOK * D_];
__device__ float g_ctx[(size_t)NTOK * D_];
__device__ float g_a[(size_t)NTOK * F_];
__device__ float g_vmean[B_ * D_];
__device__ float g_wqt[(size_t)D_ * D_];
__device__ float g_wkt[(size_t)D_ * D_];
__device__ float g_wvt[(size_t)D_ * D_];
__device__ float g_wot[(size_t)D_ * D_];
__device__ float g_w1t[(size_t)F_ * D_];
__device__ float g_w2t[(size_t)D_ * F_];

// ======================= helpers ============================================
__device__ __forceinline__ uint32_t smem_u32(const void* p) {
    uint32_t a;
    asm("{ .reg .u64 t; cvta.to.shared.u64 t, %1; cvt.u32.u64 %0, t; }"
        : "=r"(a) : "l"(p));
    return a;
}

__device__ __forceinline__ void ldsm_x4(uint32_t* r, uint32_t addr) {
    asm volatile("ldmatrix.sync.aligned.m8n8.x4.shared.b16 {%0,%1,%2,%3}, [%4];"
        : "=r"(r[0]), "=r"(r[1]), "=r"(r[2]), "=r"(r[3]) : "r"(addr));
}

__device__ __forceinline__ void mma_bf16(float* c, const uint32_t* a,
                                         uint32_t b0, uint32_t b1) {
    asm volatile(
        "mma.sync.aligned.m16n8k16.row.col.f32.bf16.bf16.f32 "
        "{%0,%1,%2,%3}, {%4,%5,%6,%7}, {%8,%9}, {%0,%1,%2,%3};"
        : "+f"(c[0]), "+f"(c[1]), "+f"(c[2]), "+f"(c[3])
        : "r"(a[0]), "r"(a[1]), "r"(a[2]), "r"(a[3]), "r"(b0), "r"(b1));
}

__device__ __forceinline__ void cvt_hilo(float4 v, uint2& hp, uint2& lp) {
    __nv_bfloat162 h01 = make_bfloat162(__float2bfloat16_rn(v.x), __float2bfloat16_rn(v.y));
    __nv_bfloat162 h23 = make_bfloat162(__float2bfloat16_rn(v.z), __float2bfloat16_rn(v.w));
    float lx = v.x - __bfloat162float(h01.x);
    float ly = v.y - __bfloat162float(h01.y);
    float lz = v.z - __bfloat162float(h23.x);
    float lw = v.w - __bfloat162float(h23.y);
    __nv_bfloat162 l01 = make_bfloat162(__float2bfloat16_rn(lx), __float2bfloat16_rn(ly));
    __nv_bfloat162 l23 = make_bfloat162(__float2bfloat16_rn(lz), __float2bfloat16_rn(lw));
    hp = make_uint2(*(uint32_t*)&h01, *(uint32_t*)&h23);
    lp = make_uint2(*(uint32_t*)&l01, *(uint32_t*)&l23);
}

__device__ __forceinline__ void pack_hilo2(float a, float b, uint32_t& hp, uint32_t& lp) {
    __nv_bfloat16 ha = __float2bfloat16_rn(a), hb = __float2bfloat16_rn(b);
    __nv_bfloat16 la = __float2bfloat16_rn(a - __bfloat162float(ha));
    __nv_bfloat16 lb = __float2bfloat16_rn(b - __bfloat162float(hb));
    __nv_bfloat162 hv = make_bfloat162(ha, hb);
    __nv_bfloat162 lv = make_bfloat162(la, lb);
    hp = *(uint32_t*)&hv;
    lp = *(uint32_t*)&lv;
}

__device__ __forceinline__ float gelu_exact(float x) {
    return 0.5f * x * (1.0f + erff(x * 0.70710678118654752f));
}

// ======================= weight transpose ===================================
__global__ __launch_bounds__(256) void transpose_kernel(
    const float* __restrict__ W, float* __restrict__ Wt, int R, int C)
{
    __shared__ float t[32][33];
    int c0 = blockIdx.x * 32, r0 = blockIdx.y * 32;
    int tx = threadIdx.x, ty = threadIdx.y;
    #pragma unroll
    for (int i = 0; i < 32; i += 8)
        t[ty + i][tx] = W[(size_t)(r0 + ty + i) * C + c0 + tx];
    __syncthreads();
    #pragma unroll
    for (int i = 0; i < 32; i += 8)
        Wt[(size_t)(c0 + ty + i) * R + r0 + tx] = t[tx][ty + i];
}

// ======================= LayerNorm ==========================================
__global__ __launch_bounds__(256) void ln_kernel(
    const float* __restrict__ x, const float* __restrict__ gamma,
    const float* __restrict__ beta, float* __restrict__ out)
{
    int row = blockIdx.x;
    int tid = threadIdx.x;
    const float* xr = x + (size_t)row * D_;
    float4 v = *(const float4*)(xr + tid * 4);
    float s  = v.x + v.y + v.z + v.w;
    float ss = v.x*v.x + v.y*v.y + v.z*v.z + v.w*v.w;
    #pragma unroll
    for (int o = 16; o > 0; o >>= 1) {
        s  += __shfl_xor_sync(0xffffffffu, s,  o);
        ss += __shfl_xor_sync(0xffffffffu, ss, o);
    }
    __shared__ float2 red[8];
    if ((tid & 31) == 0) red[tid >> 5] = make_float2(s, ss);
    __syncthreads();
    if (tid < 32) {
        float2 r = (tid < 8) ? red[tid] : make_float2(0.f, 0.f);
        s = r.x; ss = r.y;
        #pragma unroll
        for (int o = 4; o > 0; o >>= 1) {
            s  += __shfl_xor_sync(0xffffffffu, s,  o);
            ss += __shfl_xor_sync(0xffffffffu, ss, o);
        }
        if (tid == 0) red[0] = make_float2(s, ss);
    }
    __syncthreads();
    float mu  = red[0].x * (1.0f / D_);
    float var = red[0].y * (1.0f / D_) - mu * mu;
    float inv = rsqrtf(var + 1e-5f);
    float4 g4 = *(const float4*)(gamma + tid * 4);
    float4 b4 = *(const float4*)(beta  + tid * 4);
    float4 o4;
    o4.x = (v.x - mu) * inv * g4.x + b4.x;
    o4.y = (v.y - mu) * inv * g4.y + b4.y;
    o4.z = (v.z - mu) * inv * g4.z + b4.z;
    o4.w = (v.w - mu) * inv * g4.w + b4.w;
    *(float4*)(out + (size_t)row * D_ + tid * 4) = o4;
}

// ======================= HMMA GEMM (mma.sync bf16 hi/lo) ====================
#define EPI_BIAS      0
#define EPI_BIAS_RES  1
#define EPI_BIAS_GELU 2

#define ROWB   80u
#define REG_SZ (128u * ROWB)
#define OFF_AH 0u
#define OFF_AL (REG_SZ)
#define OFF_BH (2u * REG_SZ)
#define OFF_BL (3u * REG_SZ)
#define STAGE  (4u * REG_SZ)
#define MGEMM_SMEM (2 * STAGE)

template <int EPI>
__global__ __launch_bounds__(256) void mgemm_kernel(
    const float* __restrict__ A, const float* __restrict__ Bt,
    const float* __restrict__ bias, const float* __restrict__ res,
    float* __restrict__ C, int M, int N, int K)
{
    extern __shared__ __align__(128) char smem[];
    uint32_t sb = smem_u32(smem);
    int tid = threadIdx.x;
    int lane = tid & 31, wid = tid >> 5;
    int wm = wid >> 1, wn = wid & 1;
    int m0 = blockIdx.y * 128, n0 = blockIdx.x * 128;

    uint32_t aOff = (uint32_t)(wm * 32 + (lane & 15)) * ROWB + ((lane >> 4) << 4);
    uint32_t bOff = (uint32_t)(wn * 64 + (lane & 7) + ((lane >> 4) << 3)) * ROWB
                  + (((lane >> 3) & 1) << 4);

    float acc[2][8][4];
    #pragma unroll
    for (int mi = 0; mi < 2; mi++)
        #pragma unroll
        for (int ni = 0; ni < 8; ni++)
            #pragma unroll
            for (int c = 0; c < 4; c++) acc[mi][ni][c] = 0.f;

    int lr[4], lk[4];
    #pragma unroll
    for (int p = 0; p < 4; p++) {
        int idx = tid + p * 256;
        lr[p] = idx >> 3;
        lk[p] = (idx & 7) << 2;
    }

    {
        #pragma unroll
        for (int p = 0; p < 4; p++) {
            float4 va = *(const float4*)(A  + (size_t)(m0 + lr[p]) * K + lk[p]);
            float4 vb = *(const float4*)(Bt + (size_t)(n0 + lr[p]) * K + lk[p]);
            uint2 hp, lp;
            uint32_t ro = (uint32_t)lr[p] * ROWB + (uint32_t)lk[p] * 2;
            cvt_hilo(va, hp, lp);
            *(uint2*)(smem + OFF_AH + ro) = hp;
            *(uint2*)(smem + OFF_AL + ro) = lp;
            cvt_hilo(vb, hp, lp);
            *(uint2*)(smem + OFF_BH + ro) = hp;
            *(uint2*)(smem + OFF_BL + ro) = lp;
        }
    }
    __syncthreads();

    const int nIter = K >> 5;
    for (int i = 0; i < nIter; i++) {
        uint32_t st = (uint32_t)(i & 1) * STAGE;

        float4 pa[4], pb[4];
        if (i + 1 < nIter) {
            int k0 = (i + 1) << 5;
            #pragma unroll
            for (int p = 0; p < 4; p++) {
                pa[p] = *(const float4*)(A  + (size_t)(m0 + lr[p]) * K + k0 + lk[p]);
                pb[p] = *(const float4*)(Bt + (size_t)(n0 + lr[p]) * K + k0 + lk[p]);
            }
        }

        #pragma unroll
        for (int ks = 0; ks < 2; ks++) {
            uint32_t ko = (uint32_t)ks * 32;
            uint32_t a_h[2][4], a_l[2][4], b_h[4][4], b_l[4][4];
            #pragma unroll
            for (int mi = 0; mi < 2; mi++) {
                ldsm_x4(a_h[mi], sb + st + OFF_AH + aOff + ko + (uint32_t)mi * 16 * ROWB);
                ldsm_x4(a_l[mi], sb + st + OFF_AL + aOff + ko + (uint32_t)mi * 16 * ROWB);
            }
            #pragma unroll
            for (int nj = 0; nj < 4; nj++) {
                ldsm_x4(b_h[nj], sb + st + OFF_BH + bOff + ko + (uint32_t)nj * 16 * ROWB);
                ldsm_x4(b_l[nj], sb + st + OFF_BL + bOff + ko + (uint32_t)nj * 16 * ROWB);
            }
            #pragma unroll
            for (int mi = 0; mi < 2; mi++) {
                #pragma unroll
                for (int nj = 0; nj < 4; nj++) {
                    mma_bf16(acc[mi][2*nj],   a_h[mi], b_h[nj][0], b_h[nj][1]);
                    mma_bf16(acc[mi][2*nj+1], a_h[mi], b_h[nj][2], b_h[nj][3]);
                    mma_bf16(acc[mi][2*nj],   a_h[mi], b_l[nj][0], b_l[nj][1]);
                    mma_bf16(acc[mi][2*nj+1], a_h[mi], b_l[nj][2], b_l[nj][3]);
                    mma_bf16(acc[mi][2*nj],   a_l[mi], b_h[nj][0], b_h[nj][1]);
                    mma_bf16(acc[mi][2*nj+1], a_l[mi], b_h[nj][2], b_h[nj][3]);
                }
            }
        }

        if (i + 1 < nIter) {
            char* dst = smem + ((i & 1) ? 0u : STAGE);
            #pragma unroll
            for (int p = 0; p < 4; p++) {
                uint2 hp, lp;
                uint32_t ro = (uint32_t)lr[p] * ROWB + (uint32_t)lk[p] * 2;
                cvt_hilo(pa[p], hp, lp);
                *(uint2*)(dst + OFF_AH + ro) = hp;
                *(uint2*)(dst + OFF_AL + ro) = lp;
                cvt_hilo(pb[p], hp, lp);
                *(uint2*)(dst + OFF_BH + ro) = hp;
                *(uint2*)(dst + OFF_BL + ro) = lp;
            }
            __syncthreads();
        }
    }

    #pragma unroll
    for (int mi = 0; mi < 2; mi++) {
        #pragma unroll
        for (int ni = 0; ni < 8; ni++) {
            int row = m0 + wm * 32 + mi * 16 + (lane >> 2);
            int col = n0 + wn * 64 + ni * 8 + ((lane & 3) << 1);
            float* c = acc[mi][ni];
            float2 bi = *(const float2*)(bias + col);
            float2 o0 = make_float2(c[0] + bi.x, c[1] + bi.y);
            float2 o1 = make_float2(c[2] + bi.x, c[3] + bi.y);
            if (EPI == EPI_BIAS_RES) {
                float2 r0 = *(const float2*)(res + (size_t)row * N + col);
                float2 r1 = *(const float2*)(res + (size_t)(row + 8) * N + col);
                o0.x += r0.x; o0.y += r0.y; o1.x += r1.x; o1.y += r1.y;
            } else if (EPI == EPI_BIAS_GELU) {
                o0.x = gelu_exact(o0.x); o0.y = gelu_exact(o0.y);
                o1.x = gelu_exact(o1.x); o1.y = gelu_exact(o1.y);
            }
            *(float2*)(C + (size_t)row * N + col)       = o0;
            *(float2*)(C + (size_t)(row + 8) * N + col) = o1;
        }
    }
}

// ---------------- V column means (for fully-masked softmax rows) -----------
__global__ void vmean_zero(float* __restrict__ vmean) {
    vmean[blockIdx.x * 1024 + threadIdx.x] = 0.f;
}
__global__ void vmean_acc(const float* __restrict__ V, float* __restrict__ vmean) {
    int b = blockIdx.x, chunk = blockIdx.y, d = threadIdx.x;
    int s0 = chunk * 256;
    float s = 0.f;
    for (int i = 0; i < 256; i++)
        s += V[(size_t)(b * S_ + s0 + i) * D_ + d];
    atomicAdd(&vmean[b * D_ + d], s * (1.0f / S_));
}

// ======================= HMMA flash attention ===============================
// 128 queries/block (8 warps x 16 rows), 64-key tiles, dk=64.
// Q hi/lo in regs; K hi/lo in smem; V transposed hi/lo in smem.
#define AROWB   144u
#define AK_HI   0u
#define AK_LO   9216u
#define AVT_HI  18432u
#define AVT_LO  27648u
#define AQ_HI   0u
#define AQ_LO   18432u
#define ATT2_SMEM 36864

__global__ void __launch_bounds__(256, 1) attn2_kernel(
    const float* __restrict__ Q, const float* __restrict__ K,
    const float* __restrict__ V, const int* __restrict__ mask,
    const float* __restrict__ vmean, float* __restrict__ ctx)
{
    extern __shared__ __align__(128) char sm[];
    __shared__ int msk[64];
    uint32_t sb = smem_u32(sm);
    int tid = threadIdx.x, lane = tid & 31, wid = tid >> 5;
    int bh = blockIdx.y, b = bh >> 4, h = bh & 15;
    int q0 = blockIdx.x << 7;

    // ---- stage Q (scaled) into smem, pull A-fragments to registers ----
    #pragma unroll
    for (int p = 0; p < 8; p++) {
        int idx = tid + p * 256;
        int r = idx >> 4, c4 = (idx & 15) << 2;
        float4 qv = *(const float4*)(Q + (size_t)(b * S_ + q0 + r) * D_ + h * DK_ + c4);
        qv.x *= 0.125f; qv.y *= 0.125f; qv.z *= 0.125f; qv.w *= 0.125f;
        uint2 hp, lp;
        cvt_hilo(qv, hp, lp);
        *(uint2*)(sm + AQ_HI + (uint32_t)r * AROWB + (uint32_t)c4 * 2) = hp;
        *(uint2*)(sm + AQ_LO + (uint32_t)r * AROWB + (uint32_t)c4 * 2) = lp;
    }
    __syncthreads();

    uint32_t aOff = (uint32_t)(wid * 16 + (lane & 15)) * AROWB + ((lane >> 4) << 4);
    uint32_t qh[4][4], ql[4][4];
    #pragma unroll
    for (int ks = 0; ks < 4; ks++) {
        ldsm_x4(qh[ks], sb + AQ_HI + aOff + (uint32_t)ks * 32);
        ldsm_x4(ql[ks], sb + AQ_LO + aOff + (uint32_t)ks * 32);
    }

    float o[8][4];
    #pragma unroll
    for (int jf = 0; jf < 8; jf++)
        #pragma unroll
        for (int c = 0; c < 4; c++) o[jf][c] = 0.f;
    float m0 = -3.0e38f, m1 = -3.0e38f, l0 = 0.f, l1 = 0.f;

    uint32_t bOff = (uint32_t)((lane & 7) + ((lane >> 4) << 3)) * AROWB
                  + (((lane >> 3) & 1) << 4);

    const int rq0 = q0 + wid * 16 + (lane >> 2);
    const int rq1 = rq0 + 8;
    const int colb = (lane & 3) << 1;

    int jmax = (q0 + 127) >> 6;
    for (int j = 0; j <= jmax; j++) {
        int k0 = j << 6;
        __syncthreads();
        // load K (hi/lo) and V transposed (hi/lo)
        #pragma unroll
        for (int p = 0; p < 4; p++) {
            int idx = tid + p * 256;
            int r = idx >> 4, c4 = (idx & 15) << 2;
            size_t gbase = (size_t)(b * S_ + k0 + r) * D_ + h * DK_ + c4;
            float4 kv = *(const float4*)(K + gbase);
            uint2 hp, lp;
            cvt_hilo(kv, hp, lp);
            *(uint2*)(sm + AK_HI + (uint32_t)r * AROWB + (uint32_t)c4 * 2) = hp;
            *(uint2*)(sm + AK_LO + (uint32_t)r * AROWB + (uint32_t)c4 * 2) = lp;
            float4 vv = *(const float4*)(V + gbase);
            float vf[4] = {vv.x, vv.y, vv.z, vv.w};
            #pragma unroll
            for (int e = 0; e < 4; e++) {
                __nv_bfloat16 vh = __float2bfloat16_rn(vf[e]);
                __nv_bfloat16 vl = __float2bfloat16_rn(vf[e] - __bfloat162float(vh));
                uint32_t toff = (uint32_t)(c4 + e) * AROWB + (uint32_t)r * 2;
                *(__nv_bfloat16*)(sm + AVT_HI + toff) = vh;
                *(__nv_bfloat16*)(sm + AVT_LO + toff) = vl;
            }
        }
        if (tid < 64) msk[tid] = mask[b * S_ + k0 + tid];
        __syncthreads();

        // ---- QK^T (3-pass hi/lo) ----
        float s[8][4];
        #pragma unroll
        for (int jf = 0; jf < 8; jf++)
            #pragma unroll
            for (int c = 0; c < 4; c++) s[jf][c] = 0.f;
        #pragma unroll
        for (int ks = 0; ks < 4; ks++) {
            #pragma unroll
            for (int nj = 0; nj < 4; nj++) {
                uint32_t kh[4], kl[4];
                uint32_t off = bOff + (uint32_t)nj * 16 * AROWB + (uint32_t)ks * 32;
                ldsm_x4(kh, sb + AK_HI + off);
                ldsm_x4(kl, sb + AK_LO + off);
                mma_bf16(s[2*nj],   qh[ks], kh[0], kh[1]);
                mma_bf16(s[2*nj+1], qh[ks], kh[2], kh[3]);
                mma_bf16(s[2*nj],   qh[ks], kl[0], kl[1]);
                mma_bf16(s[2*nj+1], qh[ks], kl[2], kl[3]);
                mma_bf16(s[2*nj],   ql[ks], kh[0], kh[1]);
                mma_bf16(s[2*nj+1], ql[ks], kh[2], kh[3]);
            }
        }

        // ---- mask (causal + padding); exact -1e9 to match reference ----
        #pragma unroll
        for (int jf = 0; jf < 8; jf++) {
            int col = jf * 8 + colb;
            int kg = k0 + col;
            int mk0 = msk[col], mk1 = msk[col + 1];
            if (kg > rq0     || mk0 == 0) s[jf][0] = -1.0e9f;
            if (kg + 1 > rq0 || mk1 == 0) s[jf][1] = -1.0e9f;
            if (kg > rq1     || mk0 == 0) s[jf][2] = -1.0e9f;
            if (kg + 1 > rq1 || mk1 == 0) s[jf][3] = -1.0e9f;
        }

        // ---- online softmax (rows split across 4 lanes) ----
        float mt0 = -3.0e38f, mt1 = -3.0e38f;
        #pragma unroll
        for (int jf = 0; jf < 8; jf++) {
            mt0 = fmaxf(mt0, fmaxf(s[jf][0], s[jf][1]));
            mt1 = fmaxf(mt1, fmaxf(s[jf][2], s[jf][3]));
        }
        mt0 = fmaxf(mt0, __shfl_xor_sync(0xffffffffu, mt0, 1));
        mt0 = fmaxf(mt0, __shfl_xor_sync(0xffffffffu, mt0, 2));
        mt1 = fmaxf(mt1, __shfl_xor_sync(0xffffffffu, mt1, 1));
        mt1 = fmaxf(mt1, __shfl_xor_sync(0xffffffffu, mt1, 2));
        float mn0 = fmaxf(m0, mt0), mn1 = fmaxf(m1, mt1);
        float sc0 = __expf(m0 - mn0), sc1 = __expf(m1 - mn1);
        float ls0 = 0.f, ls1 = 0.f;
        #pragma unroll
        for (int jf = 0; jf < 8; jf++) {
            s[jf][0] = __expf(s[jf][0] - mn0);
            s[jf][1] = __expf(s[jf][1] - mn0);
            s[jf][2] = __expf(s[jf][2] - mn1);
            s[jf][3] = __expf(s[jf][3] - mn1);
            ls0 += s[jf][0] + s[jf][1];
            ls1 += s[jf][2] + s[jf][3];
        }
        ls0 += __shfl_xor_sync(0xffffffffu, ls0, 1);
        ls0 += __shfl_xor_sync(0xffffffffu, ls0, 2);
        ls1 += __shfl_xor_sync(0xffffffffu, ls1, 1);
        ls1 += __shfl_xor_sync(0xffffffffu, ls1, 2);
        l0 = l0 * sc0 + ls0;
        l1 = l1 * sc1 + ls1;
        m0 = mn0; m1 = mn1;
        #pragma unroll
        for (int jf = 0; jf < 8; jf++) {
            o[jf][0] *= sc0; o[jf][1] *= sc0;
            o[jf][2] *= sc1; o[jf][3] *= sc1;
        }

        // ---- P @ V (P fragments packed in registers; 3-pass hi/lo) ----
        #pragma unroll
        for (int ks = 0; ks < 4; ks++) {
            uint32_t ph[4], pl[4];
            pack_hilo2(s[2*ks][0],   s[2*ks][1],   ph[0], pl[0]);
            pack_hilo2(s[2*ks][2],   s[2*ks][3],   ph[1], pl[1]);
            pack_hilo2(s[2*ks+1][0], s[2*ks+1][1], ph[2], pl[2]);
            pack_hilo2(s[2*ks+1][2], s[2*ks+1][3], ph[3], pl[3]);
            #pragma unroll
            for (int nj = 0; nj < 4; nj++) {
                uint32_t vh[4], vl[4];
                uint32_t off = bOff + (uint32_t)nj * 16 * AROWB + (uint32_t)ks * 32;
                ldsm_x4(vh, sb + AVT_HI + off);
                ldsm_x4(vl, sb + AVT_LO + off);
                mma_bf16(o[2*nj],   ph, vh[0], vh[1]);
                mma_bf16(o[2*nj+1], ph, vh[2], vh[3]);
                mma_bf16(o[2*nj],   ph, vl[0], vl[1]);
                mma_bf16(o[2*nj+1], ph, vl[2], vl[3]);
                mma_bf16(o[2*nj],   pl, vh[0], vh[1]);
                mma_bf16(o[2*nj+1], pl, vh[2], vh[3]);
            }
        }
    }

    // ---- epilogue ----
    float inv0 = 1.0f / l0, inv1 = 1.0f / l1;
    bool dg0 = (m0 < -1.0e8f), dg1 = (m1 < -1.0e8f);
    #pragma unroll
    for (int jf = 0; jf < 8; jf++) {
        int col = h * DK_ + jf * 8 + colb;
        const float* vm = vmean + b * D_ + col;
        float2 w0, w1;
        w0.x = dg0 ? vm[0] : o[jf][0] * inv0;
        w0.y = dg0 ? vm[1] : o[jf][1] * inv0;
        w1.x = dg1 ? vm[0] : o[jf][2] * inv1;
        w1.y = dg1 ? vm[1] : o[jf][3] * inv1;
        *(float2*)(ctx + (size_t)(b * S_ + rq0) * D_ + col) = w0;
        *(float2*)(ctx + (size_t)(b * S_ + rq1) * D_ + col) = w1;
    }
}

// ---------------- launch ---------------------------------------------------
extern "C" void kernel_launch(void* const* d_in, const int* in_sizes, int n_in,
                              void* d_out, int out_size)
{
    (void)in_sizes; (void)n_in; (void)out_size;
    const float* x     = (const float*)d_in[0];
    const int*   amask = (const int*)  d_in[1];
    const float* Wq = (const float*)d_in[2];  const float* bq = (const float*)d_in[3];
    const float* Wk = (const float*)d_in[4];  const float* bk = (const float*)d_in[5];
    const float* Wv = (const float*)d_in[6];  const float* bv = (const float*)d_in[7];
    const float* Wo = (const float*)d_in[8];  const float* bo = (const float*)d_in[9];
    const float* W1 = (const float*)d_in[10]; const float* b1 = (const float*)d_in[11];
    const float* W2 = (const float*)d_in[12]; const float* b2 = (const float*)d_in[13];
    const float* g1 = (const float*)d_in[14]; const float* be1 = (const float*)d_in[15];
    const float* g2 = (const float*)d_in[16]; const float* be2 = (const float*)d_in[17];
    float* out = (float*)d_out;

    float *h, *q, *k, *v, *ctx, *a, *vmean;
    float *wqt, *wkt, *wvt, *wot, *w1t, *w2t;
    cudaGetSymbolAddress((void**)&h,     g_h);
    cudaGetSymbolAddress((void**)&q,     g_q);
    cudaGetSymbolAddress((void**)&k,     g_k);
    cudaGetSymbolAddress((void**)&v,     g_v);
    cudaGetSymbolAddress((void**)&ctx,   g_ctx);
    cudaGetSymbolAddress((void**)&a,     g_a);
    cudaGetSymbolAddress((void**)&vmean, g_vmean);
    cudaGetSymbolAddress((void**)&wqt,   g_wqt);
    cudaGetSymbolAddress((void**)&wkt,   g_wkt);
    cudaGetSymbolAddress((void**)&wvt,   g_wvt);
    cudaGetSymbolAddress((void**)&wot,   g_wot);
    cudaGetSymbolAddress((void**)&w1t,   g_w1t);
    cudaGetSymbolAddress((void**)&w2t,   g_w2t);

    cudaFuncSetAttribute(attn2_kernel, cudaFuncAttributeMaxDynamicSharedMemorySize, ATT2_SMEM);
    cudaFuncSetAttribute(mgemm_kernel<EPI_BIAS>,      cudaFuncAttributeMaxDynamicSharedMemorySize, MGEMM_SMEM);
    cudaFuncSetAttribute(mgemm_kernel<EPI_BIAS_RES>,  cudaFuncAttributeMaxDynamicSharedMemorySize, MGEMM_SMEM);
    cudaFuncSetAttribute(mgemm_kernel<EPI_BIAS_GELU>, cudaFuncAttributeMaxDynamicSharedMemorySize, MGEMM_SMEM);

    dim3 tb(32, 8);
    transpose_kernel<<<dim3(D_ / 32, D_ / 32), tb>>>(Wq, wqt, D_, D_);
    transpose_kernel<<<dim3(D_ / 32, D_ / 32), tb>>>(Wk, wkt, D_, D_);
    transpose_kernel<<<dim3(D_ / 32, D_ / 32), tb>>>(Wv, wvt, D_, D_);
    transpose_kernel<<<dim3(D_ / 32, D_ / 32), tb>>>(Wo, wot, D_, D_);
    transpose_kernel<<<dim3(F_ / 32, D_ / 32), tb>>>(W1, w1t, D_, F_);
    transpose_kernel<<<dim3(D_ / 32, F_ / 32), tb>>>(W2, w2t, F_, D_);

    dim3 gD(D_ / 128, NTOK / 128);
    dim3 gF(F_ / 128, NTOK / 128);

    ln_kernel<<<NTOK, 256>>>(x, g1, be1, h);
    mgemm_kernel<EPI_BIAS><<<gD, 256, MGEMM_SMEM>>>(h, wqt, bq, nullptr, q, NTOK, D_, D_);
    mgemm_kernel<EPI_BIAS><<<gD, 256, MGEMM_SMEM>>>(h, wkt, bk, nullptr, k, NTOK, D_, D_);
    mgemm_kernel<EPI_BIAS><<<gD, 256, MGEMM_SMEM>>>(h, wvt, bv, nullptr, v, NTOK, D_, D_);
    vmean_zero<<<4, 1024>>>(vmean);
    vmean_acc<<<dim3(4, 8), 1024>>>(v, vmean);
    attn2_kernel<<<dim3(S_ / 128, B_ * H_), 256, ATT2_SMEM>>>(q, k, v, amask, vmean, ctx);
    mgemm_kernel<EPI_BIAS_RES><<<gD, 256, MGEMM_SMEM>>>(ctx, wot, bo, x, out, NTOK, D_, D_);

    ln_kernel<<<NTOK, 256>>>(out, g2, be2, h);
    mgemm_kernel<EPI_BIAS_GELU><<<gF, 256, MGEMM_SMEM>>>(h, w1t, b1, nullptr, a, NTOK, F_, D_);
    mgemm_kernel<EPI_BIAS_RES><<<gD, 256, MGEMM_SMEM>>>(a, w2t, b2, out, out, NTOK, D_, F_);
}